// round 1
// baseline (speedup 1.0000x reference)
#include <cuda_runtime.h>
#include <cuda_bf16.h>
#include <cstdint>

// DropEmbedding: out[s,b,:] = W[X[s,b],:] * emb_row_mask(X[s,b]) * lock_mask(b,:)
//   S=2048, B=8, D=1024, V=50257
//   emb mask: (u_embed[tok] < 0.9) / 0.9          (DROPOUTE = 0.1)
//   lock mask:(u_lock[b,d]  < 0.35) / 0.35        (DROPOUTI = 0.65)
//
// Inputs (metadata order):
//   d_in[0] = X       int32  [2048*8]
//   d_in[1] = W       fp32   [50257*1024]
//   d_in[2] = u_embed fp32   [50257]
//   d_in[3] = u_lock  fp32   [8*1024]
// Output: fp32 [2048*8*1024]

#ifndef SEQ_
#define SEQ_   2048
#define BATCH_ 8
#define NINP_  1024
#endif

__global__ void __launch_bounds__(256, 8)
drop_embedding_kernel(const int*   __restrict__ X,
                      const float* __restrict__ W,
                      const float* __restrict__ u_embed,
                      const float* __restrict__ u_lock,
                      float*       __restrict__ out)
{
    constexpr float KEEP_E     = 1.0f - 0.1f;    // 0.9
    constexpr float KEEP_I     = 1.0f - 0.65f;   // 0.35
    constexpr float INV_KEEP_E = 1.0f / KEEP_E;
    constexpr float INV_KEEP_I = 1.0f / KEEP_I;

    const int tok_idx = blockIdx.x;              // s*B + b, 0..16383
    const int b       = tok_idx & (BATCH_ - 1);  // B = 8 (power of two)
    const int d4      = threadIdx.x;             // 0..255, each handles a float4

    const int token = __ldg(&X[tok_idx]);

    // Row-wise embedding dropout scale (uniform per token row)
    const float ue = __ldg(&u_embed[token]);
    const float se = (ue < KEEP_E) ? INV_KEEP_E : 0.0f;

    // Locked-dropout uniforms for this (b, d4*4 .. d4*4+3)
    const float4 l = __ldg((const float4*)(u_lock + (size_t)b * NINP_) + d4);

    float4 o;
    if (se != 0.0f) {
        // Load 16B of the embedding row only when the row survives dropout
        const float4 w = __ldg((const float4*)(W + (size_t)token * NINP_) + d4);
        o.x = w.x * se * ((l.x < KEEP_I) ? INV_KEEP_I : 0.0f);
        o.y = w.y * se * ((l.y < KEEP_I) ? INV_KEEP_I : 0.0f);
        o.z = w.z * se * ((l.z < KEEP_I) ? INV_KEEP_I : 0.0f);
        o.w = w.w * se * ((l.w < KEEP_I) ? INV_KEEP_I : 0.0f);
    } else {
        o.x = o.y = o.z = o.w = 0.0f;
    }

    ((float4*)out)[(size_t)tok_idx * (NINP_ / 4) + d4] = o;
}

extern "C" void kernel_launch(void* const* d_in, const int* in_sizes, int n_in,
                              void* d_out, int out_size)
{
    const int*   X  = (const int*)  d_in[0];
    const float* W  = (const float*)d_in[1];
    const float* ue = (const float*)d_in[2];
    const float* ul = (const float*)d_in[3];
    float*       o  = (float*)      d_out;

    (void)in_sizes; (void)n_in; (void)out_size;

    dim3 grid(SEQ_ * BATCH_);   // 16384 CTAs, one per (s,b)
    dim3 block(256);            // 256 threads * float4 = 1024 dims
    drop_embedding_kernel<<<grid, block>>>(X, W, ue, ul, o);
}

// round 2
// speedup vs baseline: 1.3565x; 1.3565x over previous
#include <cuda_runtime.h>
#include <cuda_bf16.h>
#include <cstdint>

// DropEmbedding: out[s,b,:] = W[X[s,b],:] * emb_row_mask(X[s,b]) * lock_mask(b,:)
//   S=2048, B=8, D=1024, V=50257
//
// R2: latency-bound fix. Tile CTA = (b, block of T=8 consecutive s).
//  - tokens + row-dropout scales resolved once into smem (threads 0..7)
//  - lock-mask float4 loaded & resolved ONCE per thread (b fixed in CTA)
//  - 8 predicated, independent W float4 loads front-batched per thread (MLP=8)
//
// Inputs (metadata order):
//   d_in[0] = X       int32  [2048*8]   time-major [S,B]
//   d_in[1] = W       fp32   [50257*1024]
//   d_in[2] = u_embed fp32   [50257]
//   d_in[3] = u_lock  fp32   [8*1024]
// Output: fp32 [2048*8*1024]

#define SEQ_   2048
#define BATCH_ 8
#define NINP_  1024
#define T_     8        // s-tokens per CTA

__global__ void __launch_bounds__(256)
drop_embedding_kernel(const int*   __restrict__ X,
                      const float* __restrict__ W,
                      const float* __restrict__ u_embed,
                      const float* __restrict__ u_lock,
                      float*       __restrict__ out)
{
    constexpr float KEEP_E     = 1.0f - 0.1f;    // 0.9
    constexpr float KEEP_I     = 1.0f - 0.65f;   // 0.35
    constexpr float INV_KEEP_E = 1.0f / KEEP_E;
    constexpr float INV_KEEP_I = 1.0f / KEEP_I;

    __shared__ int   s_tok[T_];
    __shared__ float s_se[T_];

    const int b  = blockIdx.y;            // 0..7
    const int s0 = blockIdx.x * T_;       // base sequence position
    const int d4 = threadIdx.x;           // 0..255 -> float4 lane over D=1024

    // Resolve tokens + embedding-row dropout scales once per CTA
    if (threadIdx.x < T_) {
        const int tok = __ldg(&X[(s0 + threadIdx.x) * BATCH_ + b]);
        s_tok[threadIdx.x] = tok;
        const float ue = __ldg(&u_embed[tok]);
        s_se[threadIdx.x] = (ue < KEEP_E) ? INV_KEEP_E : 0.0f;
    }
    __syncthreads();

    // Locked-dropout factors for (b, this float4 lane) — computed ONCE
    const float4 l = __ldg((const float4*)(u_lock + (size_t)b * NINP_) + d4);
    float4 lm;
    lm.x = (l.x < KEEP_I) ? INV_KEEP_I : 0.0f;
    lm.y = (l.y < KEEP_I) ? INV_KEEP_I : 0.0f;
    lm.z = (l.z < KEEP_I) ? INV_KEEP_I : 0.0f;
    lm.w = (l.w < KEEP_I) ? INV_KEEP_I : 0.0f;

    // Front-batch T independent (predicated) W row loads -> MLP = T
    int   tok[T_];
    float se [T_];
    float4 w [T_];
#pragma unroll
    for (int i = 0; i < T_; i++) { tok[i] = s_tok[i]; se[i] = s_se[i]; }
#pragma unroll
    for (int i = 0; i < T_; i++) {
        w[i] = make_float4(0.0f, 0.0f, 0.0f, 0.0f);
        if (se[i] != 0.0f)
            w[i] = __ldg((const float4*)(W + (size_t)tok[i] * NINP_) + d4);
    }

    // Compute + store
#pragma unroll
    for (int i = 0; i < T_; i++) {
        float4 o;
        const float s = se[i];
        o.x = w[i].x * s * lm.x;
        o.y = w[i].y * s * lm.y;
        o.z = w[i].z * s * lm.z;
        o.w = w[i].w * s * lm.w;
        ((float4*)out)[((size_t)(s0 + i) * BATCH_ + b) * (NINP_ / 4) + d4] = o;
    }
}

extern "C" void kernel_launch(void* const* d_in, const int* in_sizes, int n_in,
                              void* d_out, int out_size)
{
    const int*   X  = (const int*)  d_in[0];
    const float* W  = (const float*)d_in[1];
    const float* ue = (const float*)d_in[2];
    const float* ul = (const float*)d_in[3];
    float*       o  = (float*)      d_out;

    (void)in_sizes; (void)n_in; (void)out_size;

    dim3 grid(SEQ_ / T_, BATCH_);   // (256, 8) = 2048 CTAs
    dim3 block(256);
    drop_embedding_kernel<<<grid, block>>>(X, W, ue, ul, o);
}

// round 4
// speedup vs baseline: 1.4922x; 1.1000x over previous
#include <cuda_runtime.h>
#include <cuda_bf16.h>
#include <cstdint>

// DropEmbedding: out[s,b,:] = W[X[s,b],:] * emb_row_mask(X[s,b]) * lock_mask(b,:)
//   S=2048, B=8, D=1024, V=50257
//
// R3 (rerun after infra failure): software-pipelined streaming.
// CTA = (b, 16 tokens), depth-4 load pipeline: steady state keeps 4 independent
// W float4 loads in flight per thread while computing/storing older tokens.
// Streaming stores (__stcs) keep warm W rows in L2.
//
// Inputs (metadata order):
//   d_in[0] = X       int32  [2048*8]   time-major [S,B]
//   d_in[1] = W       fp32   [50257*1024]
//   d_in[2] = u_embed fp32   [50257]
//   d_in[3] = u_lock  fp32   [8*1024]
// Output: fp32 [2048*8*1024]

#define SEQ_   2048
#define BATCH_ 8
#define NINP_  1024
#define T_     16       // tokens per CTA
#define P_     4        // pipeline depth

__global__ void __launch_bounds__(256)
drop_embedding_kernel(const int*   __restrict__ X,
                      const float* __restrict__ W,
                      const float* __restrict__ u_embed,
                      const float* __restrict__ u_lock,
                      float*       __restrict__ out)
{
    constexpr float KEEP_E     = 1.0f - 0.1f;    // 0.9
    constexpr float KEEP_I     = 1.0f - 0.65f;   // 0.35
    constexpr float INV_KEEP_E = 1.0f / KEEP_E;
    constexpr float INV_KEEP_I = 1.0f / KEEP_I;

    __shared__ int   s_tok[T_];
    __shared__ float s_se[T_];

    const int b  = blockIdx.y;            // 0..7
    const int s0 = blockIdx.x * T_;       // base sequence position
    const int d4 = threadIdx.x;           // 0..255 -> float4 lane over D=1024

    // Resolve tokens + embedding-row dropout scales once per CTA
    if (threadIdx.x < T_) {
        const int tok = __ldg(&X[(s0 + threadIdx.x) * BATCH_ + b]);
        s_tok[threadIdx.x] = tok;
        const float ue = __ldg(&u_embed[tok]);
        s_se[threadIdx.x] = (ue < KEEP_E) ? INV_KEEP_E : 0.0f;
    }
    __syncthreads();

    // Locked-dropout factors for (b, this float4 lane) — once per thread
    const float4 l = __ldg((const float4*)(u_lock + (size_t)b * NINP_) + d4);
    float4 lm;
    lm.x = (l.x < KEEP_I) ? INV_KEEP_I : 0.0f;
    lm.y = (l.y < KEEP_I) ? INV_KEEP_I : 0.0f;
    lm.z = (l.z < KEEP_I) ? INV_KEEP_I : 0.0f;
    lm.w = (l.w < KEEP_I) ? INV_KEEP_I : 0.0f;

    float4 w[P_];

    // Prologue: fill the pipeline with P_ predicated row loads
#pragma unroll
    for (int i = 0; i < P_; i++) {
        w[i] = make_float4(0.0f, 0.0f, 0.0f, 0.0f);
        if (s_se[i] != 0.0f)
            w[i] = __ldg((const float4*)(W + (size_t)s_tok[i] * NINP_) + d4);
    }

    // Steady state: consume token i, refill slot with token i+P_
#pragma unroll
    for (int i = 0; i < T_; i++) {
        const float s = s_se[i];
        float4 o;
        o.x = w[i & (P_ - 1)].x * s * lm.x;
        o.y = w[i & (P_ - 1)].y * s * lm.y;
        o.z = w[i & (P_ - 1)].z * s * lm.z;
        o.w = w[i & (P_ - 1)].w * s * lm.w;

        // Refill before the store so the LDG issues ahead of the STG dependency
        if (i + P_ < T_) {
            float4 nw = make_float4(0.0f, 0.0f, 0.0f, 0.0f);
            if (s_se[i + P_] != 0.0f)
                nw = __ldg((const float4*)(W + (size_t)s_tok[i + P_] * NINP_) + d4);
            w[i & (P_ - 1)] = nw;
        }

        // Streaming store (evict-first): output is write-once, don't pollute L2
        __stcs(((float4*)out) + ((size_t)(s0 + i) * BATCH_ + b) * (NINP_ / 4) + d4, o);
    }
}

extern "C" void kernel_launch(void* const* d_in, const int* in_sizes, int n_in,
                              void* d_out, int out_size)
{
    const int*   X  = (const int*)  d_in[0];
    const float* W  = (const float*)d_in[1];
    const float* ue = (const float*)d_in[2];
    const float* ul = (const float*)d_in[3];
    float*       o  = (float*)      d_out;

    (void)in_sizes; (void)n_in; (void)out_size;

    dim3 grid(SEQ_ / T_, BATCH_);   // (128, 8) = 1024 CTAs
    dim3 block(256);
    drop_embedding_kernel<<<grid, block>>>(X, W, ue, ul, o);
}